// round 6
// baseline (speedup 1.0000x reference)
#include <cuda_runtime.h>
#include <cuda_bf16.h>

// Problem constants: B=1024, N=16, T=256
#define BB 1024
#define NN 16
#define TT 256
#define GRID (BB * 2)   // 2 CTAs per batch (t split 0..127 / 128..255)

__device__ float g_partial[GRID];
__device__ unsigned int g_count = 0;

// ---- compile-time slot maps -------------------------------------------------
// Half A (lanes 0-15): triangle rows 0..10  -> 66 slots
// Half B (lanes 16-31): triangle rows 11..15 (full cols 0..i) -> 70 slots
__device__ __forceinline__ constexpr int sA(int i, int j) { return i*(i+1)/2 + j; }
__device__ __forceinline__ constexpr int sB(int i, int j) { return i*(i+1)/2 - 66 + j; }

__host__ __device__ constexpr int eA_of(int s) {           // slot -> element i*16+j
    if (s >= 66) return 0;                                 // pad slots: dup elem 0
    int i = 0; while ((i+1)*(i+2)/2 <= s) ++i;
    return i*16 + (s - i*(i+1)/2);
}
__host__ __device__ constexpr int eB_of(int s) {
    int i = 11; while (i*(i+1)/2 - 66 + (i+1) <= s) ++i;
    return i*16 + (s - (i*(i+1)/2 - 66));
}

// Uniform load: every lane issues the same LDG; address selected per half by a SEL.
template <int S>
__device__ __forceinline__ void load_cov(float (&v)[70], const float* __restrict__ covbt, int half) {
    constexpr int ea = eA_of(S);
    constexpr int eb = eB_of(S);
    v[S] = covbt[(half ? eb : ea) * TT];
    if constexpr (S + 1 < 70) load_cov<S + 1>(v, covbt, half);
}

__global__ __launch_bounds__(256, 2)
void gll_pair_kernel(const float* __restrict__ pred,
                     const float* __restrict__ tgt,
                     const float* __restrict__ cov,
                     float* __restrict__ out)
{
    const int tid  = threadIdx.x;
    const int lane = tid & 31;
    const int w    = tid >> 5;
    const int half = lane >> 4;                       // 0: rows 0-10, 1: rows 11-15
    const int b    = blockIdx.x >> 1;
    const int t    = ((blockIdx.x & 1) << 7) + (w << 4) + (lane & 15);

    const float* covbt = cov + ((size_t)b * (NN*NN)) * TT + t;

    // ---- big coalesced load burst: 70 LDGs into shared physical registers ----
    float v[70];
    load_cov<0>(v, covbt, half);

    // ---- border diff: half A owns rows 0..10, half B rows 11..15 ----
    float bvv[11];
    {
        const float* pb = pred + ((size_t)b * NN) * TT + t;
        const float* gb = tgt  + ((size_t)b * NN) * TT + t;
#pragma unroll
        for (int s = 0; s < 11; s++) {
            bvv[s] = 0.0f;
            if (!half || s < 5) {
                const int n = half ? (11 + s) : s;
                bvv[s] = pb[n * TT] - gb[n * TT];
            }
        }
    }

    // ---- bordered LDL^T, row-partitioned across the lane pair ----
    float quad = 0.0f, prod = 1.0f;
    const unsigned FULL = 0xffffffffu;

    // Steps 0..10: pivot owned by half A. Broadcast r, tb, and column
    // multipliers w_k (k<=10) to half B via shuffles at converged points.
#pragma unroll
    for (int j = 0; j < 11; j++) {
        float r_loc = 0.0f, tb_loc = 0.0f;
        float wcol[11];
#pragma unroll
        for (int k = 0; k < 11; k++) wcol[k] = 0.0f;

        if (half == 0) {
            const float d = v[sA(j, j)];
            r_loc = __fdividef(1.0f, d);
            prod *= d;
            tb_loc = bvv[j] * r_loc;
            quad  += bvv[j] * tb_loc;
#pragma unroll
            for (int k = j + 1; k <= 10; k++) wcol[k] = v[sA(k, j)] * r_loc;
        }

        const int src = lane & 15;                    // low lane of the pair
        const float tb = __shfl_sync(FULL, tb_loc, src);
        const float r  = __shfl_sync(FULL, r_loc,  src);
        float wb[11];
#pragma unroll
        for (int k = j + 1; k <= 10; k++) wb[k] = __shfl_sync(FULL, wcol[k], src);

        if (half == 0) {
#pragma unroll
            for (int k = j + 1; k <= 10; k++) bvv[k] -= v[sA(k, j)] * tb;
#pragma unroll
            for (int k = j + 1; k <= 10; k++) {
                const float wk = wb[k];
#pragma unroll
                for (int i = k; i <= 10; i++) v[sA(i, k)] -= v[sA(i, j)] * wk;
            }
        } else {
#pragma unroll
            for (int k = 11; k <= 15; k++) bvv[k - 11] -= v[sB(k, j)] * tb;
            // columns j+1..10: multiplier comes from half A
#pragma unroll
            for (int k = j + 1; k <= 10; k++) {
                const float wk = wb[k];
#pragma unroll
                for (int i = 11; i <= 15; i++) v[sB(i, k)] -= v[sB(i, j)] * wk;
            }
            // columns 11..15: self-contained
#pragma unroll
            for (int k = 11; k <= 15; k++) {
                const float wk = v[sB(k, j)] * r;
#pragma unroll
                for (int i = k; i <= 15; i++) v[sB(i, k)] -= v[sB(i, j)] * wk;
            }
        }
    }

    // Steps 11..15: entirely inside half B, no shuffles.
#pragma unroll
    for (int j = 11; j < 16; j++) {
        if (half == 1) {
            const float d = v[sB(j, j)];
            const float r = __fdividef(1.0f, d);
            prod *= d;
            const float tb = bvv[j - 11] * r;
            quad += bvv[j - 11] * tb;
#pragma unroll
            for (int k = j + 1; k <= 15; k++) bvv[k - 11] -= v[sB(k, j)] * tb;
#pragma unroll
            for (int k = j + 1; k <= 15; k++) {
                const float wk = v[sB(k, j)] * r;
#pragma unroll
                for (int i = k; i <= 15; i++) v[sB(i, k)] -= v[sB(i, j)] * wk;
            }
        }
    }

    // ---- combine pair halves: quad_A + quad_B + log(prod_A * prod_B) ----
    float partial = quad + __logf(prod);
    partial += __shfl_xor_sync(FULL, partial, 16);

    // ---- deterministic in-block reduction over 128 (b,t) values ----
    __shared__ float red[128];
    if (half == 0) red[w * 16 + (lane & 15)] = partial;
    __syncthreads();
#pragma unroll
    for (int off = 64; off > 0; off >>= 1) {
        if (tid < off) red[tid] += red[tid + off];
        __syncthreads();
    }

    // ---- last-block deterministic final reduction (double) ----
    __shared__ bool s_last;
    if (tid == 0) {
        g_partial[blockIdx.x] = red[0];
        __threadfence();
        s_last = (atomicAdd(&g_count, 1u) == GRID - 1u);
    }
    __syncthreads();

    if (s_last) {
        __shared__ double dred[256];
        double s = 0.0;
#pragma unroll
        for (int m = 0; m < GRID / 256; m++) s += (double)g_partial[tid + m * 256];
        dred[tid] = s;
        __syncthreads();
#pragma unroll
        for (int off = 128; off > 0; off >>= 1) {
            if (tid < off) dred[tid] += dred[tid + off];
            __syncthreads();
        }
        if (tid == 0) {
            out[0] = (float)(dred[0] / (double)((size_t)BB * TT));
            g_count = 0;   // reset for next graph replay
        }
    }
}

extern "C" void kernel_launch(void* const* d_in, const int* in_sizes, int n_in,
                              void* d_out, int out_size)
{
    const float* pred = (const float*)d_in[0];  // prediction [B,N,T]
    const float* tgt  = (const float*)d_in[1];  // target     [B,N,T]
    const float* cov  = (const float*)d_in[2];  // cov        [B,N,N,T]
    float* out = (float*)d_out;

    gll_pair_kernel<<<GRID, 256>>>(pred, tgt, cov, out);
}